// round 10
// baseline (speedup 1.0000x reference)
#include <cuda_runtime.h>
#include <cuda_bf16.h>
#include <cstdint>

#define NB 32
#define C 128
#define HW 3136
#define K3 384
#define NSPLIT 3
#define SPL ((size_t)NB * C * K3)

// A tiles: 128 rows x [hi 32 | lo 32] bf16 = 128B + 16 pad = 144B stride
#define RS 144
#define TILE_A (128 * RS)                     // 18432
// gemm2 B tile (transposed): 64 rows (hi 32 + lo 32) x 128 p-cols = 256B + 16 pad
#define RSB 272
#define TILE_B2 (64 * RSB)                    // 17408
#define STAGE1 (2 * TILE_A)                   // gemm1: A + B
#define STAGE2 (TILE_A + TILE_B2)             // gemm2: A + Bt
// raw scratch: gemm1 = p2w slice 128 rows x 32 floats (128B row)
#define RAW1 16384
// gemm2 = x windows: 12 channel rows x 136 floats (544B row)
#define RAW2R 544
#define RAW2 (12 * RAW2R)                     // 6528 -> pad
#define RAW2P 6656
#define SMEM1 (1024 + 2 * STAGE1 + 2 * RAW1)  // 107520
#define SMEM2 (1024 + 2 * STAGE2 + 2 * RAW2P) // 86016

__device__ float g_t8[NB * 4 * HW];
__device__ float g_t7p[NSPLIT * NB * C * K3];
__device__ __nv_bfloat16 g_t6hi[(size_t)NB * C * HW];
__device__ __nv_bfloat16 g_t6lo[(size_t)NB * C * HW];
__device__ __nv_bfloat16 g_t7hi[(size_t)NB * C * K3];
__device__ __nv_bfloat16 g_t7lo[(size_t)NB * C * K3];

// ---------------- helpers ----------------
__device__ __forceinline__ uint32_t smem_u32(const void* p) {
    uint32_t a;
    asm("{ .reg .u64 t; cvta.to.shared.u64 t, %1; cvt.u32.u64 %0, t; }" : "=r"(a) : "l"(p));
    return a;
}
#define CP16(dst, src) \
    asm volatile("cp.async.cg.shared.global [%0], [%1], 16;" :: "r"(dst), "l"(src))
#define CP_COMMIT() asm volatile("cp.async.commit_group;" ::: "memory")
#define CP_WAIT0()  asm volatile("cp.async.wait_group 0;" ::: "memory")

__device__ __forceinline__ void ldsm4(uint32_t addr, uint32_t* r) {
    asm volatile("ldmatrix.sync.aligned.m8n8.x4.shared.b16 {%0,%1,%2,%3}, [%4];"
                 : "=r"(r[0]), "=r"(r[1]), "=r"(r[2]), "=r"(r[3]) : "r"(addr));
}
__device__ __forceinline__ void ldsm4t(uint32_t addr, uint32_t* r) {
    asm volatile("ldmatrix.sync.aligned.m8n8.x4.trans.shared.b16 {%0,%1,%2,%3}, [%4];"
                 : "=r"(r[0]), "=r"(r[1]), "=r"(r[2]), "=r"(r[3]) : "r"(addr));
}
__device__ __forceinline__ void mma16816(float* c, const uint32_t a[4],
                                         uint32_t b0, uint32_t b1) {
    asm volatile(
        "mma.sync.aligned.m16n8k16.row.col.f32.bf16.bf16.f32 "
        "{%0,%1,%2,%3}, {%4,%5,%6,%7}, {%8,%9}, {%0,%1,%2,%3};"
        : "+f"(c[0]), "+f"(c[1]), "+f"(c[2]), "+f"(c[3])
        : "r"(a[0]), "r"(a[1]), "r"(a[2]), "r"(a[3]), "r"(b0), "r"(b1));
}
__device__ __forceinline__ void split4(const float v[4], uint2& hi, uint2& lo) {
    __nv_bfloat16 h0 = __float2bfloat16(v[0]), h1 = __float2bfloat16(v[1]);
    __nv_bfloat16 h2 = __float2bfloat16(v[2]), h3 = __float2bfloat16(v[3]);
    __nv_bfloat16 l0 = __float2bfloat16(v[0] - __bfloat162float(h0));
    __nv_bfloat16 l1 = __float2bfloat16(v[1] - __bfloat162float(h1));
    __nv_bfloat16 l2 = __float2bfloat16(v[2] - __bfloat162float(h2));
    __nv_bfloat16 l3 = __float2bfloat16(v[3] - __bfloat162float(h3));
    hi.x = (uint32_t)__bfloat16_as_ushort(h0) | ((uint32_t)__bfloat16_as_ushort(h1) << 16);
    hi.y = (uint32_t)__bfloat16_as_ushort(h2) | ((uint32_t)__bfloat16_as_ushort(h3) << 16);
    lo.x = (uint32_t)__bfloat16_as_ushort(l0) | ((uint32_t)__bfloat16_as_ushort(l1) << 16);
    lo.y = (uint32_t)__bfloat16_as_ushort(l2) | ((uint32_t)__bfloat16_as_ushort(l3) << 16);
}

// cp.async one A tile: 128 rows x [hi 64B | lo 64B] from packed bf16 planes
__device__ __forceinline__ void cpA(char* Asp, const __nv_bfloat16* hi,
                                    const __nv_bfloat16* lo, size_t rstride,
                                    int col0, int tid) {
    #pragma unroll
    for (int it = 0; it < 2; it++) {
        int idx = tid + it * 256;
        int r = idx >> 2, s = idx & 3;
        CP16(smem_u32(Asp + r * RS + s * 16),
             hi + (size_t)r * rstride + col0 + s * 8);
    }
    #pragma unroll
    for (int it = 0; it < 2; it++) {
        int idx = tid + it * 256;
        int r = idx >> 2, s = idx & 3;
        CP16(smem_u32(Asp + r * RS + 64 + s * 16),
             lo + (size_t)r * rstride + col0 + s * 8);
    }
}

// 3 product passes over preloaded fragments
#define MMA_PASSES(acc, ah, al, bh, bl, ldA_lo)                         \
    do {                                                                \
        _Pragma("unroll")                                               \
        for (int mi = 0; mi < 2; mi++)                                  \
            _Pragma("unroll")                                           \
            for (int nq = 0; nq < 4; nq++) {                            \
                mma16816(acc[mi][nq * 2],     ah[mi], bh[nq][0], bh[nq][1]); \
                mma16816(acc[mi][nq * 2 + 1], ah[mi], bh[nq][2], bh[nq][3]); \
            }                                                           \
        _Pragma("unroll")                                               \
        for (int mi = 0; mi < 2; mi++)                                  \
            _Pragma("unroll")                                           \
            for (int nq = 0; nq < 4; nq++) {                            \
                mma16816(acc[mi][nq * 2],     ah[mi], bl[nq][0], bl[nq][1]); \
                mma16816(acc[mi][nq * 2 + 1], ah[mi], bl[nq][2], bl[nq][3]); \
            }                                                           \
        ldA_lo;                                                         \
        _Pragma("unroll")                                               \
        for (int mi = 0; mi < 2; mi++)                                  \
            _Pragma("unroll")                                           \
            for (int nq = 0; nq < 4; nq++) {                            \
                mma16816(acc[mi][nq * 2],     al[mi], bh[nq][0], bh[nq][1]); \
                mma16816(acc[mi][nq * 2 + 1], al[mi], bh[nq][2], bh[nq][3]); \
            }                                                           \
    } while (0)

__device__ __forceinline__ void mma_g1(uint32_t As, uint32_t Bs, int wr, int wc,
                                       int lane, float acc[2][8][4]) {
    const uint32_t a_row = (uint32_t)(wr * 32 + (lane & 15)) * RS + ((lane >> 4) << 4);
    const int brow = (lane & 7) + ((lane & 16) >> 1);
    const uint32_t b_k = (uint32_t)((lane & 8) << 1);
    #pragma unroll
    for (int ks = 0; ks < 2; ks++) {
        uint32_t k16 = ks * 32;
        uint32_t ah[2][4], al[2][4], bh[4][4], bl[4][4];
        #pragma unroll
        for (int mi = 0; mi < 2; mi++)
            ldsm4(As + a_row + (uint32_t)(mi * 16) * RS + k16, ah[mi]);
        #pragma unroll
        for (int nq = 0; nq < 4; nq++) {
            uint32_t bbase = Bs + (uint32_t)(wc * 64 + nq * 16 + brow) * RS + k16 + b_k;
            ldsm4(bbase,      bh[nq]);
            ldsm4(bbase + 64, bl[nq]);
        }
        MMA_PASSES(acc, ah, al, bh, bl,
            { _Pragma("unroll")
              for (int mi = 0; mi < 2; mi++)
                  ldsm4(As + a_row + (uint32_t)(mi * 16) * RS + k16 + 64, al[mi]); });
    }
}

__device__ __forceinline__ void mma_g2(uint32_t As, uint32_t Bs, int wr, int wc,
                                       int lane, float acc[2][8][4]) {
    const uint32_t a_row = (uint32_t)(wr * 32 + (lane & 15)) * RS + ((lane >> 4) << 4);
    const uint32_t b_row = (uint32_t)((lane & 7) + (lane & 8));
    const uint32_t b_pofs = (uint32_t)((lane & 16));
    #pragma unroll
    for (int ks = 0; ks < 2; ks++) {
        uint32_t k16 = ks * 32;
        uint32_t mb = ks * 16;
        uint32_t ah[2][4], al[2][4], bh[4][4], bl[4][4];
        #pragma unroll
        for (int mi = 0; mi < 2; mi++)
            ldsm4(As + a_row + (uint32_t)(mi * 16) * RS + k16, ah[mi]);
        #pragma unroll
        for (int nq = 0; nq < 4; nq++) {
            uint32_t addr = Bs + (mb + b_row) * RSB
                          + (uint32_t)(wc * 64 + nq * 16) * 2 + b_pofs;
            ldsm4t(addr,            bh[nq]);
            ldsm4t(addr + 32 * RSB, bl[nq]);
        }
        MMA_PASSES(acc, ah, al, bh, bl,
            { _Pragma("unroll")
              for (int mi = 0; mi < 2; mi++)
                  ldsm4(As + a_row + (uint32_t)(mi * 16) * RS + k16 + 64, al[mi]); });
    }
}

// ---------------------------------------------------------------------------
// prep: t8 reduction + packed t6 hi/lo planes. grid (98, 32) x 256
// ---------------------------------------------------------------------------
__global__ void __launch_bounds__(256) prep_kernel(const float* __restrict__ x,
                                                   const float* __restrict__ p5w,
                                                   const float* __restrict__ conv_w) {
    __shared__ float red[8][4][32];
    int n = blockIdx.y;
    int tid = threadIdx.x;
    int pl = tid & 31, q = tid >> 5;
    int p = blockIdx.x * 32 + pl;
    int rp = (p >= 56) ? (p - 56) : (p + 3080);

    const float* xb = x + (size_t)n * C * HW;
    __nv_bfloat16* t6h = g_t6hi + (size_t)n * C * HW;
    __nv_bfloat16* t6l = g_t6lo + (size_t)n * C * HW;

    float s0 = 0.f, s1 = 0.f, s2 = 0.f, s3 = 0.f;
    int c0 = q * 16;
    #pragma unroll 4
    for (int i = 0; i < 16; i++) {
        int c = c0 + i;
        float xp = xb[(size_t)c * HW + p];
        float xr = xb[(size_t)c * HW + rp];
        float v = xp + xr;
        __nv_bfloat16 h = __float2bfloat16(v);
        t6h[(size_t)c * HW + p] = h;
        t6l[(size_t)c * HW + p] = __float2bfloat16(v - __bfloat162float(h));
        float t = __ldg(&p5w[c]) * xr;
        s0 = fmaf(__ldg(&conv_w[c]),       t, s0);
        s1 = fmaf(__ldg(&conv_w[128 + c]), t, s1);
        s2 = fmaf(__ldg(&conv_w[256 + c]), t, s2);
        s3 = fmaf(__ldg(&conv_w[384 + c]), t, s3);
    }
    red[q][0][pl] = s0; red[q][1][pl] = s1; red[q][2][pl] = s2; red[q][3][pl] = s3;
    __syncthreads();
    if (tid < 128) {
        int j = tid >> 5, pl2 = tid & 31;
        float r = 0.f;
        #pragma unroll
        for (int qq = 0; qq < 8; qq++) r += red[qq][j][pl2];
        g_t8[((size_t)n * 4 + j) * HW + blockIdx.x * 32 + pl2] = r;
    }
}

// ---------------------------------------------------------------------------
// gemm1: D rows = c' (A = t6 planes via cp.async), cols = m.
// B = p2w * unfold_h(x); p2w slice cp.async'd raw, converted from smem.
// grid (3, 32, 3) x 256, occ 2
// ---------------------------------------------------------------------------
__device__ __forceinline__ void cpRawW(char* raw, const float* p2w,
                                       int m0, int p0, int tid) {
    #pragma unroll
    for (int it = 0; it < 4; it++) {
        int idx = tid + it * 256;             // 0..1023
        int row = idx >> 3, s = idx & 7;
        CP16(smem_u32(raw + row * 128 + s * 16),
             p2w + (size_t)(m0 + row) * HW + p0 + s * 4);
    }
}

__device__ __forceinline__ void g1_convert(char* Bsp, const char* raw,
                                           const float* xb, int m0, int p0, int tid) {
    int col4 = (tid & 7) * 4;
    int rbase = tid >> 3;
    #pragma unroll
    for (int pass = 0; pass < 4; pass++) {
        int mr = rbase + pass * 32;
        int m = m0 + mr, c = m / 3, k = m - 3 * c, sh = 2 * k - 2;
        float4 w4 = *reinterpret_cast<const float4*>(raw + mr * 128 + col4 * 4);
        int p = p0 + col4;
        int hh = p / 56 + sh;
        float v[4] = {0.f, 0.f, 0.f, 0.f};
        if (hh >= 0 && hh < 56) {
            float4 x4 = *reinterpret_cast<const float4*>(
                xb + (size_t)c * HW + p + sh * 56);
            v[0] = w4.x * x4.x; v[1] = w4.y * x4.y;
            v[2] = w4.z * x4.z; v[3] = w4.w * x4.w;
        }
        uint2 hi, lo; split4(v, hi, lo);
        char* bb = Bsp + mr * RS + col4 * 2;
        *(uint2*)(bb)      = hi;
        *(uint2*)(bb + 64) = lo;
    }
}

__global__ void __launch_bounds__(256, 2) gemm1_kernel(const float* __restrict__ x,
                                                       const float* __restrict__ p2w) {
    extern __shared__ char smem_raw[];
    char* smp = (char*)(((uintptr_t)smem_raw + 1023) & ~(uintptr_t)1023);
    char* rawb = smp + 2 * STAGE1;

    const int tid = threadIdx.x, lane = tid & 31, wid = tid >> 5;
    const int wr = wid >> 1, wc = wid & 1;
    const int n = blockIdx.y, m0 = blockIdx.x * 128, s = blockIdx.z;

    const float* xb = x + (size_t)n * C * HW;
    const __nv_bfloat16* t6h = g_t6hi + (size_t)n * C * HW;
    const __nv_bfloat16* t6l = g_t6lo + (size_t)n * C * HW;

    float acc[2][8][4] = {};
    const int beg[4] = {0, 33, 66, 98};
    const int nch = beg[s + 1] - beg[s];
    const int pbase = beg[s] * 32;

    // prologue: raw(0); then A(0)+raw(1); convert B(0)
    cpRawW(rawb, p2w, m0, pbase, tid);
    CP_COMMIT();
    CP_WAIT0();
    __syncthreads();
    cpA(smp, t6h, t6l, HW, pbase, tid);
    if (nch > 1) cpRawW(rawb + RAW1, p2w, m0, pbase + 32, tid);
    CP_COMMIT();
    g1_convert(smp + TILE_A, rawb, xb, m0, pbase, tid);
    CP_WAIT0();

    for (int ch = 0; ch < nch; ch++) {
        __syncthreads();      // publish tiles(ch), raw(ch+1)
        char* cur = smp + (ch & 1) * STAGE1;
        if (ch + 1 < nch) {
            char* nxt = smp + ((ch + 1) & 1) * STAGE1;
            cpA(nxt, t6h, t6l, HW, pbase + (ch + 1) * 32, tid);
            if (ch + 2 < nch)
                cpRawW(rawb + ((ch + 2) & 1) * RAW1, p2w, m0,
                       pbase + (ch + 2) * 32, tid);
            CP_COMMIT();
            g1_convert(nxt + TILE_A, rawb + ((ch + 1) & 1) * RAW1,
                       xb, m0, pbase + (ch + 1) * 32, tid);
        }
        mma_g1(smem_u32(cur), smem_u32(cur + TILE_A), wr, wc, lane, acc);
        CP_WAIT0();
    }

    const float SC = 9.1126371e-4f;   // 1/(sqrt(3136)*sqrt(384))
    float* ob = g_t7p + ((size_t)(s * NB + n)) * C * K3;
    #pragma unroll
    for (int mi = 0; mi < 2; mi++) {
        #pragma unroll
        for (int ni = 0; ni < 8; ni++) {
            int row = wr * 32 + mi * 16 + (lane >> 2);
            int col = m0 + wc * 64 + ni * 8 + (lane & 3) * 2;
            *(float2*)(ob + (size_t)row * K3 + col) =
                make_float2(acc[mi][ni][0] * SC, acc[mi][ni][1] * SC);
            *(float2*)(ob + (size_t)(row + 8) * K3 + col) =
                make_float2(acc[mi][ni][2] * SC, acc[mi][ni][3] * SC);
        }
    }
}

// ---------------------------------------------------------------------------
// t7sum: sum 3 partials, pack to hi/lo planes. grid 1536 x 256
// ---------------------------------------------------------------------------
__global__ void __launch_bounds__(256) t7sum_kernel() {
    size_t i = ((size_t)blockIdx.x * 256 + threadIdx.x) * 4;
    float4 v0 = *(const float4*)(g_t7p + i);
    float4 v1 = *(const float4*)(g_t7p + SPL + i);
    float4 v2 = *(const float4*)(g_t7p + 2 * SPL + i);
    float v[4] = {v0.x + v1.x + v2.x, v0.y + v1.y + v2.y,
                  v0.z + v1.z + v2.z, v0.w + v1.w + v2.w};
    uint2 hi, lo; split4(v, hi, lo);
    *(uint2*)(g_t7hi + i) = hi;
    *(uint2*)(g_t7lo + i) = lo;
}

// ---------------------------------------------------------------------------
// gemm2: D rows = c (A = t7 planes via cp.async), cols = p (128-tile).
// B = unfold_w(x); raw x windows cp.async'd, converted from smem.
// grid (25, 32) x 256, occ 2
// ---------------------------------------------------------------------------
__device__ __forceinline__ void cpRaw2(char* raw, const float* xb,
                                       int p0, int m0c, int tid) {
    int c0 = m0c / 3;
    int srcoff = (p0 >= 4) ? (p0 - 4) : 0;
    int len = HW - srcoff; if (len > 136) len = 136;
    int nseg = len >> 2;                        // 16B segments per row
    #pragma unroll
    for (int it = 0; it < 2; it++) {
        int idx = tid + it * 256;               // 0..511, need 12*nseg <= 408
        int row = idx / 34, s = idx - row * 34;
        if (row < 12 && s < nseg) {
            int c = c0 + row; if (c > 127) c = 127;
            CP16(smem_u32(raw + row * RAW2R + s * 16),
                 xb + (size_t)c * HW + srcoff + s * 4);
        }
    }
}

__device__ __forceinline__ void g2_convert(char* Bsp, const char* raw,
                                           int p0, int m0c, int tid) {
    int mrow = tid & 31;
    int pq = tid >> 5;
    int c0 = m0c / 3;
    int srcoff = (p0 >= 4) ? (p0 - 4) : 0;
    int m = m0c + mrow, cp = m / 3, k = m - 3 * cp, sh = 2 * k - 2;
    const float* rawrow = (const float*)(raw + (cp - c0) * RAW2R);
    int pbase = p0 + pq * 16;

    float v[16];
    #pragma unroll
    for (int j = 0; j < 8; j++) {
        int p = pbase + 2 * j;
        int wcol = p % 56;
        int ww = wcol + sh;
        bool ok = (p < HW) && (ww >= 0) && (ww < 56);
        float2 f = *(const float2*)(rawrow + (p + sh - srcoff));
        v[2 * j]     = ok ? f.x : 0.f;
        v[2 * j + 1] = ok ? f.y : 0.f;
    }
    uint2 hi[4], lo[4];
    #pragma unroll
    for (int q = 0; q < 4; q++) split4(v + 4 * q, hi[q], lo[q]);
    char* bh = Bsp + mrow * RSB + pq * 32;
    char* bl = Bsp + (32 + mrow) * RSB + pq * 32;
    *(uint4*)(bh)      = make_uint4(hi[0].x, hi[0].y, hi[1].x, hi[1].y);
    *(uint4*)(bh + 16) = make_uint4(hi[2].x, hi[2].y, hi[3].x, hi[3].y);
    *(uint4*)(bl)      = make_uint4(lo[0].x, lo[0].y, lo[1].x, lo[1].y);
    *(uint4*)(bl + 16) = make_uint4(lo[2].x, lo[2].y, lo[3].x, lo[3].y);
}

__global__ void __launch_bounds__(256, 2) gemm2_kernel(const float* __restrict__ x,
                                                       float* __restrict__ out) {
    extern __shared__ char smem_raw[];
    char* smp = (char*)(((uintptr_t)smem_raw + 1023) & ~(uintptr_t)1023);
    char* rawb = smp + 2 * STAGE2;

    const int tid = threadIdx.x, lane = tid & 31, wid = tid >> 5;
    const int wr = wid >> 1, wc = wid & 1;
    const int n = blockIdx.y, p0 = blockIdx.x * 128;

    const float* xb = x + (size_t)n * C * HW;
    const __nv_bfloat16* t7h = g_t7hi + (size_t)n * C * K3;
    const __nv_bfloat16* t7l = g_t7lo + (size_t)n * C * K3;

    float acc[2][8][4] = {};
    const int NCH = 12;

    // prologue
    cpRaw2(rawb, xb, p0, 0, tid);
    CP_COMMIT();
    CP_WAIT0();
    __syncthreads();
    cpA(smp, t7h, t7l, K3, 0, tid);
    cpRaw2(rawb + RAW2P, xb, p0, 32, tid);
    CP_COMMIT();
    g2_convert(smp + TILE_A, rawb, p0, 0, tid);
    CP_WAIT0();

    for (int ch = 0; ch < NCH; ch++) {
        __syncthreads();
        char* cur = smp + (ch & 1) * STAGE2;
        if (ch + 1 < NCH) {
            char* nxt = smp + ((ch + 1) & 1) * STAGE2;
            cpA(nxt, t7h, t7l, K3, (ch + 1) * 32, tid);
            if (ch + 2 < NCH)
                cpRaw2(rawb + ((ch + 2) & 1) * RAW2P, xb, p0, (ch + 2) * 32, tid);
            CP_COMMIT();
            g2_convert(nxt + TILE_A, rawb + ((ch + 1) & 1) * RAW2P,
                       p0, (ch + 1) * 32, tid);
        }
        mma_g2(smem_u32(cur), smem_u32(cur + TILE_A), wr, wc, lane, acc);
        CP_WAIT0();
    }

    // epilogue: out = acc + x * t8[c%4]
    const float* t8b = g_t8 + (size_t)n * 4 * HW;
    float* outb = out + (size_t)n * C * HW;
    #pragma unroll
    for (int mi = 0; mi < 2; mi++) {
        #pragma unroll
        for (int ni = 0; ni < 8; ni++) {
            int c = wr * 32 + mi * 16 + (lane >> 2);
            int p = p0 + wc * 64 + ni * 8 + (lane & 3) * 2;
            if (p < HW) {
                #pragma unroll
                for (int h = 0; h < 2; h++) {
                    int cc = c + h * 8;
                    float2 xv  = *(const float2*)(xb  + (size_t)cc * HW + p);
                    float2 t8v = *(const float2*)(t8b + (size_t)(cc & 3) * HW + p);
                    float2 o = make_float2(acc[mi][ni][2 * h]     + xv.x * t8v.x,
                                           acc[mi][ni][2 * h + 1] + xv.y * t8v.y);
                    *(float2*)(outb + (size_t)cc * HW + p) = o;
                }
            }
        }
    }
}

// ---------------------------------------------------------------------------
extern "C" void kernel_launch(void* const* d_in, const int* in_sizes, int n_in,
                              void* d_out, int out_size) {
    const float* x      = (const float*)d_in[0];
    const float* p2w    = (const float*)d_in[1];
    const float* p5w    = (const float*)d_in[2];
    const float* conv_w = (const float*)d_in[3];
    float* out = (float*)d_out;

    cudaFuncSetAttribute(gemm1_kernel, cudaFuncAttributeMaxDynamicSharedMemorySize, SMEM1);
    cudaFuncSetAttribute(gemm2_kernel, cudaFuncAttributeMaxDynamicSharedMemorySize, SMEM2);

    prep_kernel<<<dim3(98, NB), 256>>>(x, p5w, conv_w);
    gemm1_kernel<<<dim3(3, NB, NSPLIT), 256, SMEM1>>>(x, p2w);
    t7sum_kernel<<<1536, 256>>>();
    gemm2_kernel<<<dim3(25, NB), 256, SMEM2>>>(x, out);
}

// round 11
// speedup vs baseline: 1.0743x; 1.0743x over previous
#include <cuda_runtime.h>
#include <cuda_bf16.h>
#include <cstdint>

#define NB 32
#define C 128
#define HW 3136
#define K3 384
#define NSPLIT 3
#define SPL ((size_t)NB * C * K3)

// A tiles: 128 rows x [hi 32 | lo 32] bf16 = 128B + 16 pad = 144B stride
#define RS 144
#define TILE_A (128 * RS)                     // 18432
// gemm2 B tile (transposed): 64 rows (hi 32 + lo 32) x 128 p-cols = 256B + 16 pad
#define RSB 272
#define TILE_B2 (64 * RSB)                    // 17408
#define STAGE1 (2 * TILE_A)
#define STAGE2 (TILE_A + TILE_B2)
#define SMEM1 (2 * STAGE1 + 1024)
#define SMEM2 (2 * STAGE2 + 1024)

__device__ float g_t8[NB * 4 * HW];
__device__ float g_t7p[NSPLIT * NB * C * K3];
__device__ __nv_bfloat16 g_t6hi[(size_t)NB * C * HW];
__device__ __nv_bfloat16 g_t6lo[(size_t)NB * C * HW];
__device__ __nv_bfloat16 g_t7hi[(size_t)NB * C * K3];
__device__ __nv_bfloat16 g_t7lo[(size_t)NB * C * K3];

// ---------------- helpers ----------------
__device__ __forceinline__ uint32_t smem_u32(const void* p) {
    uint32_t a;
    asm("{ .reg .u64 t; cvta.to.shared.u64 t, %1; cvt.u32.u64 %0, t; }" : "=r"(a) : "l"(p));
    return a;
}
#define CP16(dst, src) \
    asm volatile("cp.async.cg.shared.global [%0], [%1], 16;" :: "r"(dst), "l"(src))
#define CP_COMMIT() asm volatile("cp.async.commit_group;" ::: "memory")
#define CP_WAIT0()  asm volatile("cp.async.wait_group 0;" ::: "memory")

__device__ __forceinline__ void ldsm4(uint32_t addr, uint32_t* r) {
    asm volatile("ldmatrix.sync.aligned.m8n8.x4.shared.b16 {%0,%1,%2,%3}, [%4];"
                 : "=r"(r[0]), "=r"(r[1]), "=r"(r[2]), "=r"(r[3]) : "r"(addr));
}
__device__ __forceinline__ void ldsm4t(uint32_t addr, uint32_t* r) {
    asm volatile("ldmatrix.sync.aligned.m8n8.x4.trans.shared.b16 {%0,%1,%2,%3}, [%4];"
                 : "=r"(r[0]), "=r"(r[1]), "=r"(r[2]), "=r"(r[3]) : "r"(addr));
}
__device__ __forceinline__ void mma16816(float* c, const uint32_t a[4],
                                         uint32_t b0, uint32_t b1) {
    asm volatile(
        "mma.sync.aligned.m16n8k16.row.col.f32.bf16.bf16.f32 "
        "{%0,%1,%2,%3}, {%4,%5,%6,%7}, {%8,%9}, {%0,%1,%2,%3};"
        : "+f"(c[0]), "+f"(c[1]), "+f"(c[2]), "+f"(c[3])
        : "r"(a[0]), "r"(a[1]), "r"(a[2]), "r"(a[3]), "r"(b0), "r"(b1));
}
__device__ __forceinline__ void split4(const float v[4], uint2& hi, uint2& lo) {
    __nv_bfloat16 h0 = __float2bfloat16(v[0]), h1 = __float2bfloat16(v[1]);
    __nv_bfloat16 h2 = __float2bfloat16(v[2]), h3 = __float2bfloat16(v[3]);
    __nv_bfloat16 l0 = __float2bfloat16(v[0] - __bfloat162float(h0));
    __nv_bfloat16 l1 = __float2bfloat16(v[1] - __bfloat162float(h1));
    __nv_bfloat16 l2 = __float2bfloat16(v[2] - __bfloat162float(h2));
    __nv_bfloat16 l3 = __float2bfloat16(v[3] - __bfloat162float(h3));
    hi.x = (uint32_t)__bfloat16_as_ushort(h0) | ((uint32_t)__bfloat16_as_ushort(h1) << 16);
    hi.y = (uint32_t)__bfloat16_as_ushort(h2) | ((uint32_t)__bfloat16_as_ushort(h3) << 16);
    lo.x = (uint32_t)__bfloat16_as_ushort(l0) | ((uint32_t)__bfloat16_as_ushort(l1) << 16);
    lo.y = (uint32_t)__bfloat16_as_ushort(l2) | ((uint32_t)__bfloat16_as_ushort(l3) << 16);
}

// cp.async one A tile: 128 rows x [hi 64B | lo 64B], 128 threads
__device__ __forceinline__ void cpA(char* Asp, const __nv_bfloat16* hi,
                                    const __nv_bfloat16* lo, size_t rstride,
                                    int col0, int tid) {
    #pragma unroll
    for (int it = 0; it < 4; it++) {
        int idx = tid + it * 128;
        int r = idx >> 2, s = idx & 3;
        CP16(smem_u32(Asp + r * RS + s * 16),
             hi + (size_t)r * rstride + col0 + s * 8);
    }
    #pragma unroll
    for (int it = 0; it < 4; it++) {
        int idx = tid + it * 128;
        int r = idx >> 2, s = idx & 3;
        CP16(smem_u32(Asp + r * RS + 64 + s * 16),
             lo + (size_t)r * rstride + col0 + s * 8);
    }
}

// 3 product passes, 64x64 warp tile: mi 0..3, nq 0..3
#define MMA_PASSES(acc, ah, al, bh, bl, ldA_lo)                         \
    do {                                                                \
        _Pragma("unroll")                                               \
        for (int mi = 0; mi < 4; mi++)                                  \
            _Pragma("unroll")                                           \
            for (int nq = 0; nq < 4; nq++) {                            \
                mma16816(acc[mi][nq * 2],     ah[mi], bh[nq][0], bh[nq][1]); \
                mma16816(acc[mi][nq * 2 + 1], ah[mi], bh[nq][2], bh[nq][3]); \
            }                                                           \
        _Pragma("unroll")                                               \
        for (int mi = 0; mi < 4; mi++)                                  \
            _Pragma("unroll")                                           \
            for (int nq = 0; nq < 4; nq++) {                            \
                mma16816(acc[mi][nq * 2],     ah[mi], bl[nq][0], bl[nq][1]); \
                mma16816(acc[mi][nq * 2 + 1], ah[mi], bl[nq][2], bl[nq][3]); \
            }                                                           \
        ldA_lo;                                                         \
        _Pragma("unroll")                                               \
        for (int mi = 0; mi < 4; mi++)                                  \
            _Pragma("unroll")                                           \
            for (int nq = 0; nq < 4; nq++) {                            \
                mma16816(acc[mi][nq * 2],     al[mi], bh[nq][0], bh[nq][1]); \
                mma16816(acc[mi][nq * 2 + 1], al[mi], bh[nq][2], bh[nq][3]); \
            }                                                           \
    } while (0)

// gemm1 MMA: warp tile 64x64. wr,wc in {0,1}
__device__ __forceinline__ void mma_g1(uint32_t As, uint32_t Bs, int wr, int wc,
                                       int lane, float acc[4][8][4]) {
    const uint32_t a_row = (uint32_t)(wr * 64 + (lane & 15)) * RS + ((lane >> 4) << 4);
    const int brow = (lane & 7) + ((lane & 16) >> 1);
    const uint32_t b_k = (uint32_t)((lane & 8) << 1);
    #pragma unroll
    for (int ks = 0; ks < 2; ks++) {
        uint32_t k16 = ks * 32;
        uint32_t ah[4][4], al[4][4], bh[4][4], bl[4][4];
        #pragma unroll
        for (int mi = 0; mi < 4; mi++)
            ldsm4(As + a_row + (uint32_t)(mi * 16) * RS + k16, ah[mi]);
        #pragma unroll
        for (int nq = 0; nq < 4; nq++) {
            uint32_t bbase = Bs + (uint32_t)(wc * 64 + nq * 16 + brow) * RS + k16 + b_k;
            ldsm4(bbase,      bh[nq]);
            ldsm4(bbase + 64, bl[nq]);
        }
        MMA_PASSES(acc, ah, al, bh, bl,
            { _Pragma("unroll")
              for (int mi = 0; mi < 4; mi++)
                  ldsm4(As + a_row + (uint32_t)(mi * 16) * RS + k16 + 64, al[mi]); });
    }
}

// gemm2 MMA: B transposed [m 32+32][p 128]
__device__ __forceinline__ void mma_g2(uint32_t As, uint32_t Bs, int wr, int wc,
                                       int lane, float acc[4][8][4]) {
    const uint32_t a_row = (uint32_t)(wr * 64 + (lane & 15)) * RS + ((lane >> 4) << 4);
    const uint32_t b_row = (uint32_t)((lane & 7) + (lane & 8));
    const uint32_t b_pofs = (uint32_t)((lane & 16));
    #pragma unroll
    for (int ks = 0; ks < 2; ks++) {
        uint32_t k16 = ks * 32;
        uint32_t mb = ks * 16;
        uint32_t ah[4][4], al[4][4], bh[4][4], bl[4][4];
        #pragma unroll
        for (int mi = 0; mi < 4; mi++)
            ldsm4(As + a_row + (uint32_t)(mi * 16) * RS + k16, ah[mi]);
        #pragma unroll
        for (int nq = 0; nq < 4; nq++) {
            uint32_t addr = Bs + (mb + b_row) * RSB
                          + (uint32_t)(wc * 64 + nq * 16) * 2 + b_pofs;
            ldsm4t(addr,            bh[nq]);
            ldsm4t(addr + 32 * RSB, bl[nq]);
        }
        MMA_PASSES(acc, ah, al, bh, bl,
            { _Pragma("unroll")
              for (int mi = 0; mi < 4; mi++)
                  ldsm4(As + a_row + (uint32_t)(mi * 16) * RS + k16 + 64, al[mi]); });
    }
}

// ---------------------------------------------------------------------------
// prep: t8 reduction + packed t6 hi/lo planes. grid (98, 32) x 256
// ---------------------------------------------------------------------------
__global__ void __launch_bounds__(256) prep_kernel(const float* __restrict__ x,
                                                   const float* __restrict__ p5w,
                                                   const float* __restrict__ conv_w) {
    __shared__ float red[8][4][32];
    int n = blockIdx.y;
    int tid = threadIdx.x;
    int pl = tid & 31, q = tid >> 5;
    int p = blockIdx.x * 32 + pl;
    int rp = (p >= 56) ? (p - 56) : (p + 3080);

    const float* xb = x + (size_t)n * C * HW;
    __nv_bfloat16* t6h = g_t6hi + (size_t)n * C * HW;
    __nv_bfloat16* t6l = g_t6lo + (size_t)n * C * HW;

    float s0 = 0.f, s1 = 0.f, s2 = 0.f, s3 = 0.f;
    int c0 = q * 16;
    #pragma unroll 4
    for (int i = 0; i < 16; i++) {
        int c = c0 + i;
        float xp = xb[(size_t)c * HW + p];
        float xr = xb[(size_t)c * HW + rp];
        float v = xp + xr;
        __nv_bfloat16 h = __float2bfloat16(v);
        t6h[(size_t)c * HW + p] = h;
        t6l[(size_t)c * HW + p] = __float2bfloat16(v - __bfloat162float(h));
        float t = __ldg(&p5w[c]) * xr;
        s0 = fmaf(__ldg(&conv_w[c]),       t, s0);
        s1 = fmaf(__ldg(&conv_w[128 + c]), t, s1);
        s2 = fmaf(__ldg(&conv_w[256 + c]), t, s2);
        s3 = fmaf(__ldg(&conv_w[384 + c]), t, s3);
    }
    red[q][0][pl] = s0; red[q][1][pl] = s1; red[q][2][pl] = s2; red[q][3][pl] = s3;
    __syncthreads();
    if (tid < 128) {
        int j = tid >> 5, pl2 = tid & 31;
        float r = 0.f;
        #pragma unroll
        for (int qq = 0; qq < 8; qq++) r += red[qq][j][pl2];
        g_t8[((size_t)n * 4 + j) * HW + blockIdx.x * 32 + pl2] = r;
    }
}

// ---------------------------------------------------------------------------
// gemm1: 128-thread CTA (4 warps, 64x64 tiles). K chunks of 32, 98/3 splits.
// ---------------------------------------------------------------------------
__device__ __forceinline__ void g1_stageB(char* Bsp, const float* xb,
                                          const float* p2w, int m0, int p0, int tid) {
    int col4 = (tid & 7) * 4;
    int rbase = tid >> 3;        // 0..15
    #pragma unroll
    for (int pass = 0; pass < 8; pass++) {
        int mr = rbase + pass * 16;
        int m = m0 + mr, c = m / 3, k = m - 3 * c, sh = 2 * k - 2;
        float4 w4 = *reinterpret_cast<const float4*>(p2w + (size_t)m * HW + p0 + col4);
        int p = p0 + col4;
        int hh = p / 56 + sh;
        float v[4] = {0.f, 0.f, 0.f, 0.f};
        if (hh >= 0 && hh < 56) {
            float4 x4 = *reinterpret_cast<const float4*>(
                xb + (size_t)c * HW + p + sh * 56);
            v[0] = w4.x * x4.x; v[1] = w4.y * x4.y;
            v[2] = w4.z * x4.z; v[3] = w4.w * x4.w;
        }
        uint2 hi, lo; split4(v, hi, lo);
        char* bb = Bsp + mr * RS + col4 * 2;
        *(uint2*)(bb)      = hi;
        *(uint2*)(bb + 64) = lo;
    }
}

__global__ void __launch_bounds__(128, 2) gemm1_kernel(const float* __restrict__ x,
                                                       const float* __restrict__ p2w) {
    extern __shared__ char smem_raw[];
    char* smp = (char*)(((uintptr_t)smem_raw + 1023) & ~(uintptr_t)1023);

    const int tid = threadIdx.x, lane = tid & 31, wid = tid >> 5;
    const int wr = wid >> 1, wc = wid & 1;
    const int n = blockIdx.y, m0 = blockIdx.x * 128, s = blockIdx.z;

    const float* xb = x + (size_t)n * C * HW;
    const __nv_bfloat16* t6h = g_t6hi + (size_t)n * C * HW;
    const __nv_bfloat16* t6l = g_t6lo + (size_t)n * C * HW;

    float acc[4][8][4] = {};
    const int beg[4] = {0, 33, 66, 98};
    const int nch = beg[s + 1] - beg[s];
    const int pbase = beg[s] * 32;

    cpA(smp, t6h, t6l, HW, pbase, tid);
    CP_COMMIT();
    g1_stageB(smp + TILE_A, xb, p2w, m0, pbase, tid);
    CP_WAIT0();
    __syncthreads();

    for (int ch = 0; ch < nch; ch++) {
        char* cur = smp + (ch & 1) * STAGE1;
        bool more = ch + 1 < nch;
        char* nxt = smp + ((ch + 1) & 1) * STAGE1;
        int pn = pbase + (ch + 1) * 32;
        if (more) { cpA(nxt, t6h, t6l, HW, pn, tid); CP_COMMIT(); }
        mma_g1(smem_u32(cur), smem_u32(cur + TILE_A), wr, wc, lane, acc);
        if (more) g1_stageB(nxt + TILE_A, xb, p2w, m0, pn, tid);
        CP_WAIT0();
        __syncthreads();
    }

    const float SC = 9.1126371e-4f;   // 1/(sqrt(3136)*sqrt(384))
    float* ob = g_t7p + ((size_t)(s * NB + n)) * C * K3;
    #pragma unroll
    for (int mi = 0; mi < 4; mi++) {
        #pragma unroll
        for (int ni = 0; ni < 8; ni++) {
            int row = wr * 64 + mi * 16 + (lane >> 2);
            int col = m0 + wc * 64 + ni * 8 + (lane & 3) * 2;
            *(float2*)(ob + (size_t)row * K3 + col) =
                make_float2(acc[mi][ni][0] * SC, acc[mi][ni][1] * SC);
            *(float2*)(ob + (size_t)(row + 8) * K3 + col) =
                make_float2(acc[mi][ni][2] * SC, acc[mi][ni][3] * SC);
        }
    }
}

// ---------------------------------------------------------------------------
// t7sum: sum 3 partials, pack to hi/lo planes. grid 1536 x 256
// ---------------------------------------------------------------------------
__global__ void __launch_bounds__(256) t7sum_kernel() {
    size_t i = ((size_t)blockIdx.x * 256 + threadIdx.x) * 4;
    float4 v0 = *(const float4*)(g_t7p + i);
    float4 v1 = *(const float4*)(g_t7p + SPL + i);
    float4 v2 = *(const float4*)(g_t7p + 2 * SPL + i);
    float v[4] = {v0.x + v1.x + v2.x, v0.y + v1.y + v2.y,
                  v0.z + v1.z + v2.z, v0.w + v1.w + v2.w};
    uint2 hi, lo; split4(v, hi, lo);
    *(uint2*)(g_t7hi + i) = hi;
    *(uint2*)(g_t7lo + i) = lo;
}

// ---------------------------------------------------------------------------
// gemm2: 128-thread CTA (4 warps, 64x64 tiles). K = 384, 12 chunks of 32.
// ---------------------------------------------------------------------------
__device__ __forceinline__ void g2_stageB(char* Bsp, const float* xb,
                                          int p0, int m0c, int tid) {
    int mrow = tid & 31;
    int pq0 = tid >> 5;          // 0..3; handle pq0 and pq0+4
    int m = m0c + mrow, cp = m / 3, k = m - 3 * cp, sh = 2 * k - 2;
    const float* srcrow = xb + (size_t)cp * HW + sh;
    #pragma unroll
    for (int half = 0; half < 2; half++) {
        int pq = pq0 + half * 4;
        int pbase = p0 + pq * 16;
        float v[16];
        #pragma unroll
        for (int j = 0; j < 8; j++) {
            int p = pbase + 2 * j;
            int wcol = p % 56;
            int ww = wcol + sh;
            bool ok = (p < HW) && (ww >= 0) && (ww < 56);
            float2 f = ok ? *(const float2*)(srcrow + p) : make_float2(0.f, 0.f);
            v[2 * j] = f.x; v[2 * j + 1] = f.y;
        }
        uint2 hi[4], lo[4];
        #pragma unroll
        for (int q = 0; q < 4; q++) split4(v + 4 * q, hi[q], lo[q]);
        char* bh = Bsp + mrow * RSB + pq * 32;
        char* bl = Bsp + (32 + mrow) * RSB + pq * 32;
        *(uint4*)(bh)      = make_uint4(hi[0].x, hi[0].y, hi[1].x, hi[1].y);
        *(uint4*)(bh + 16) = make_uint4(hi[2].x, hi[2].y, hi[3].x, hi[3].y);
        *(uint4*)(bl)      = make_uint4(lo[0].x, lo[0].y, lo[1].x, lo[1].y);
        *(uint4*)(bl + 16) = make_uint4(lo[2].x, lo[2].y, lo[3].x, lo[3].y);
    }
}

__global__ void __launch_bounds__(128, 2) gemm2_kernel(const float* __restrict__ x,
                                                       float* __restrict__ out) {
    extern __shared__ char smem_raw[];
    char* smp = (char*)(((uintptr_t)smem_raw + 1023) & ~(uintptr_t)1023);

    const int tid = threadIdx.x, lane = tid & 31, wid = tid >> 5;
    const int wr = wid >> 1, wc = wid & 1;
    const int n = blockIdx.y, p0 = blockIdx.x * 128;

    const float* xb = x + (size_t)n * C * HW;
    const __nv_bfloat16* t7h = g_t7hi + (size_t)n * C * K3;
    const __nv_bfloat16* t7l = g_t7lo + (size_t)n * C * K3;

    float acc[4][8][4] = {};
    const int NCH = 12;

    cpA(smp, t7h, t7l, K3, 0, tid);
    CP_COMMIT();
    g2_stageB(smp + TILE_A, xb, p0, 0, tid);
    CP_WAIT0();
    __syncthreads();

    for (int ch = 0; ch < NCH; ch++) {
        char* cur = smp + (ch & 1) * STAGE2;
        bool more = ch + 1 < NCH;
        char* nxt = smp + ((ch + 1) & 1) * STAGE2;
        int mn = (ch + 1) * 32;
        if (more) { cpA(nxt, t7h, t7l, K3, mn, tid); CP_COMMIT(); }
        mma_g2(smem_u32(cur), smem_u32(cur + TILE_A), wr, wc, lane, acc);
        if (more) g2_stageB(nxt + TILE_A, xb, p0, mn, tid);
        CP_WAIT0();
        __syncthreads();
    }

    // epilogue: out = acc + x * t8[c%4]
    const float* t8b = g_t8 + (size_t)n * 4 * HW;
    float* outb = out + (size_t)n * C * HW;
    #pragma unroll
    for (int mi = 0; mi < 4; mi++) {
        #pragma unroll
        for (int ni = 0; ni < 8; ni++) {
            int c = wr * 64 + mi * 16 + (lane >> 2);
            int p = p0 + wc * 64 + ni * 8 + (lane & 3) * 2;
            if (p < HW) {
                #pragma unroll
                for (int h = 0; h < 2; h++) {
                    int cc = c + h * 8;
                    float2 xv  = *(const float2*)(xb  + (size_t)cc * HW + p);
                    float2 t8v = *(const float2*)(t8b + (size_t)(cc & 3) * HW + p);
                    float2 o = make_float2(acc[mi][ni][2 * h]     + xv.x * t8v.x,
                                           acc[mi][ni][2 * h + 1] + xv.y * t8v.y);
                    *(float2*)(outb + (size_t)cc * HW + p) = o;
                }
            }
        }
    }
}

// ---------------------------------------------------------------------------
extern "C" void kernel_launch(void* const* d_in, const int* in_sizes, int n_in,
                              void* d_out, int out_size) {
    const float* x      = (const float*)d_in[0];
    const float* p2w    = (const float*)d_in[1];
    const float* p5w    = (const float*)d_in[2];
    const float* conv_w = (const float*)d_in[3];
    float* out = (float*)d_out;

    cudaFuncSetAttribute(gemm1_kernel, cudaFuncAttributeMaxDynamicSharedMemorySize, SMEM1);
    cudaFuncSetAttribute(gemm2_kernel, cudaFuncAttributeMaxDynamicSharedMemorySize, SMEM2);

    prep_kernel<<<dim3(98, NB), 256>>>(x, p5w, conv_w);
    gemm1_kernel<<<dim3(3, NB, NSPLIT), 128, SMEM1>>>(x, p2w);
    t7sum_kernel<<<1536, 256>>>();
    gemm2_kernel<<<dim3(25, NB), 128, SMEM2>>>(x, out);
}

// round 12
// speedup vs baseline: 1.1942x; 1.1116x over previous
#include <cuda_runtime.h>
#include <cuda_bf16.h>
#include <cstdint>

#define NB 32
#define C 128
#define HW 3136
#define K3 384
#define NSPLIT 3
#define SPL ((size_t)NB * C * K3)

// A tiles: 128 rows x [hi 32 | lo 32] bf16 = 128B + 16 pad = 144B stride
#define RS 144
#define TILE_A (128 * RS)                     // 18432
// gemm2 B tile (transposed): 64 rows (hi 32 + lo 32) x 128 p-cols = 256B + 16 pad
#define RSB 272
#define TILE_B2 (64 * RSB)                    // 17408
#define STAGE1 (2 * TILE_A)
#define STAGE2 (TILE_A + TILE_B2)
#define SMEM1 (2 * STAGE1 + 1024)
#define SMEM2 (2 * STAGE2 + 1024)

#define G2_TILES 800                          // 32 batches x 25 p-tiles
#define G2_GRID 592                           // 148 SM x 2 CTAs

__device__ float g_t8[NB * 4 * HW];
__device__ float g_t7p[NSPLIT * NB * C * K3];
__device__ __nv_bfloat16 g_t6hi[(size_t)NB * C * HW];
__device__ __nv_bfloat16 g_t6lo[(size_t)NB * C * HW];
__device__ __nv_bfloat16 g_t7hi[(size_t)NB * C * K3];
__device__ __nv_bfloat16 g_t7lo[(size_t)NB * C * K3];

// ---------------- helpers ----------------
__device__ __forceinline__ uint32_t smem_u32(const void* p) {
    uint32_t a;
    asm("{ .reg .u64 t; cvta.to.shared.u64 t, %1; cvt.u32.u64 %0, t; }" : "=r"(a) : "l"(p));
    return a;
}
#define CP16(dst, src) \
    asm volatile("cp.async.cg.shared.global [%0], [%1], 16;" :: "r"(dst), "l"(src))
#define CP_COMMIT() asm volatile("cp.async.commit_group;" ::: "memory")
#define CP_WAIT0()  asm volatile("cp.async.wait_group 0;" ::: "memory")

__device__ __forceinline__ void ldsm4(uint32_t addr, uint32_t* r) {
    asm volatile("ldmatrix.sync.aligned.m8n8.x4.shared.b16 {%0,%1,%2,%3}, [%4];"
                 : "=r"(r[0]), "=r"(r[1]), "=r"(r[2]), "=r"(r[3]) : "r"(addr));
}
__device__ __forceinline__ void ldsm4t(uint32_t addr, uint32_t* r) {
    asm volatile("ldmatrix.sync.aligned.m8n8.x4.trans.shared.b16 {%0,%1,%2,%3}, [%4];"
                 : "=r"(r[0]), "=r"(r[1]), "=r"(r[2]), "=r"(r[3]) : "r"(addr));
}
__device__ __forceinline__ void mma16816(float* c, const uint32_t a[4],
                                         uint32_t b0, uint32_t b1) {
    asm volatile(
        "mma.sync.aligned.m16n8k16.row.col.f32.bf16.bf16.f32 "
        "{%0,%1,%2,%3}, {%4,%5,%6,%7}, {%8,%9}, {%0,%1,%2,%3};"
        : "+f"(c[0]), "+f"(c[1]), "+f"(c[2]), "+f"(c[3])
        : "r"(a[0]), "r"(a[1]), "r"(a[2]), "r"(a[3]), "r"(b0), "r"(b1));
}
__device__ __forceinline__ void split4(const float v[4], uint2& hi, uint2& lo) {
    __nv_bfloat16 h0 = __float2bfloat16(v[0]), h1 = __float2bfloat16(v[1]);
    __nv_bfloat16 h2 = __float2bfloat16(v[2]), h3 = __float2bfloat16(v[3]);
    __nv_bfloat16 l0 = __float2bfloat16(v[0] - __bfloat162float(h0));
    __nv_bfloat16 l1 = __float2bfloat16(v[1] - __bfloat162float(h1));
    __nv_bfloat16 l2 = __float2bfloat16(v[2] - __bfloat162float(h2));
    __nv_bfloat16 l3 = __float2bfloat16(v[3] - __bfloat162float(h3));
    hi.x = (uint32_t)__bfloat16_as_ushort(h0) | ((uint32_t)__bfloat16_as_ushort(h1) << 16);
    hi.y = (uint32_t)__bfloat16_as_ushort(h2) | ((uint32_t)__bfloat16_as_ushort(h3) << 16);
    lo.x = (uint32_t)__bfloat16_as_ushort(l0) | ((uint32_t)__bfloat16_as_ushort(l1) << 16);
    lo.y = (uint32_t)__bfloat16_as_ushort(l2) | ((uint32_t)__bfloat16_as_ushort(l3) << 16);
}

// cp.async one A tile: 128 rows x [hi 64B | lo 64B] from packed bf16 planes
__device__ __forceinline__ void cpA(char* Asp, const __nv_bfloat16* hi,
                                    const __nv_bfloat16* lo, size_t rstride,
                                    int col0, int tid) {
    #pragma unroll
    for (int it = 0; it < 2; it++) {
        int idx = tid + it * 256;
        int r = idx >> 2, s = idx & 3;
        CP16(smem_u32(Asp + r * RS + s * 16),
             hi + (size_t)r * rstride + col0 + s * 8);
    }
    #pragma unroll
    for (int it = 0; it < 2; it++) {
        int idx = tid + it * 256;
        int r = idx >> 2, s = idx & 3;
        CP16(smem_u32(Asp + r * RS + 64 + s * 16),
             lo + (size_t)r * rstride + col0 + s * 8);
    }
}

// 3 product passes over preloaded fragments
#define MMA_PASSES(acc, ah, al, bh, bl, ldA_lo)                         \
    do {                                                                \
        _Pragma("unroll")                                               \
        for (int mi = 0; mi < 2; mi++)                                  \
            _Pragma("unroll")                                           \
            for (int nq = 0; nq < 4; nq++) {                            \
                mma16816(acc[mi][nq * 2],     ah[mi], bh[nq][0], bh[nq][1]); \
                mma16816(acc[mi][nq * 2 + 1], ah[mi], bh[nq][2], bh[nq][3]); \
            }                                                           \
        _Pragma("unroll")                                               \
        for (int mi = 0; mi < 2; mi++)                                  \
            _Pragma("unroll")                                           \
            for (int nq = 0; nq < 4; nq++) {                            \
                mma16816(acc[mi][nq * 2],     ah[mi], bl[nq][0], bl[nq][1]); \
                mma16816(acc[mi][nq * 2 + 1], ah[mi], bl[nq][2], bl[nq][3]); \
            }                                                           \
        ldA_lo;                                                         \
        _Pragma("unroll")                                               \
        for (int mi = 0; mi < 2; mi++)                                  \
            _Pragma("unroll")                                           \
            for (int nq = 0; nq < 4; nq++) {                            \
                mma16816(acc[mi][nq * 2],     al[mi], bh[nq][0], bh[nq][1]); \
                mma16816(acc[mi][nq * 2 + 1], al[mi], bh[nq][2], bh[nq][3]); \
            }                                                           \
    } while (0)

__device__ __forceinline__ void mma_g1(uint32_t As, uint32_t Bs, int wr, int wc,
                                       int lane, float acc[2][8][4]) {
    const uint32_t a_row = (uint32_t)(wr * 32 + (lane & 15)) * RS + ((lane >> 4) << 4);
    const int brow = (lane & 7) + ((lane & 16) >> 1);
    const uint32_t b_k = (uint32_t)((lane & 8) << 1);
    #pragma unroll
    for (int ks = 0; ks < 2; ks++) {
        uint32_t k16 = ks * 32;
        uint32_t ah[2][4], al[2][4], bh[4][4], bl[4][4];
        #pragma unroll
        for (int mi = 0; mi < 2; mi++)
            ldsm4(As + a_row + (uint32_t)(mi * 16) * RS + k16, ah[mi]);
        #pragma unroll
        for (int nq = 0; nq < 4; nq++) {
            uint32_t bbase = Bs + (uint32_t)(wc * 64 + nq * 16 + brow) * RS + k16 + b_k;
            ldsm4(bbase,      bh[nq]);
            ldsm4(bbase + 64, bl[nq]);
        }
        MMA_PASSES(acc, ah, al, bh, bl,
            { _Pragma("unroll")
              for (int mi = 0; mi < 2; mi++)
                  ldsm4(As + a_row + (uint32_t)(mi * 16) * RS + k16 + 64, al[mi]); });
    }
}

__device__ __forceinline__ void mma_g2(uint32_t As, uint32_t Bs, int wr, int wc,
                                       int lane, float acc[2][8][4]) {
    const uint32_t a_row = (uint32_t)(wr * 32 + (lane & 15)) * RS + ((lane >> 4) << 4);
    const uint32_t b_row = (uint32_t)((lane & 7) + (lane & 8));
    const uint32_t b_pofs = (uint32_t)((lane & 16));
    #pragma unroll
    for (int ks = 0; ks < 2; ks++) {
        uint32_t k16 = ks * 32;
        uint32_t mb = ks * 16;
        uint32_t ah[2][4], al[2][4], bh[4][4], bl[4][4];
        #pragma unroll
        for (int mi = 0; mi < 2; mi++)
            ldsm4(As + a_row + (uint32_t)(mi * 16) * RS + k16, ah[mi]);
        #pragma unroll
        for (int nq = 0; nq < 4; nq++) {
            uint32_t addr = Bs + (mb + b_row) * RSB
                          + (uint32_t)(wc * 64 + nq * 16) * 2 + b_pofs;
            ldsm4t(addr,            bh[nq]);
            ldsm4t(addr + 32 * RSB, bl[nq]);
        }
        MMA_PASSES(acc, ah, al, bh, bl,
            { _Pragma("unroll")
              for (int mi = 0; mi < 2; mi++)
                  ldsm4(As + a_row + (uint32_t)(mi * 16) * RS + k16 + 64, al[mi]); });
    }
}

// ---------------------------------------------------------------------------
// prep: t8 reduction + packed t6 hi/lo planes. grid (98, 32) x 256
// ---------------------------------------------------------------------------
__global__ void __launch_bounds__(256) prep_kernel(const float* __restrict__ x,
                                                   const float* __restrict__ p5w,
                                                   const float* __restrict__ conv_w) {
    __shared__ float red[8][4][32];
    int n = blockIdx.y;
    int tid = threadIdx.x;
    int pl = tid & 31, q = tid >> 5;
    int p = blockIdx.x * 32 + pl;
    int rp = (p >= 56) ? (p - 56) : (p + 3080);

    const float* xb = x + (size_t)n * C * HW;
    __nv_bfloat16* t6h = g_t6hi + (size_t)n * C * HW;
    __nv_bfloat16* t6l = g_t6lo + (size_t)n * C * HW;

    float s0 = 0.f, s1 = 0.f, s2 = 0.f, s3 = 0.f;
    int c0 = q * 16;
    #pragma unroll 4
    for (int i = 0; i < 16; i++) {
        int c = c0 + i;
        float xp = xb[(size_t)c * HW + p];
        float xr = xb[(size_t)c * HW + rp];
        float v = xp + xr;
        __nv_bfloat16 h = __float2bfloat16(v);
        t6h[(size_t)c * HW + p] = h;
        t6l[(size_t)c * HW + p] = __float2bfloat16(v - __bfloat162float(h));
        float t = __ldg(&p5w[c]) * xr;
        s0 = fmaf(__ldg(&conv_w[c]),       t, s0);
        s1 = fmaf(__ldg(&conv_w[128 + c]), t, s1);
        s2 = fmaf(__ldg(&conv_w[256 + c]), t, s2);
        s3 = fmaf(__ldg(&conv_w[384 + c]), t, s3);
    }
    red[q][0][pl] = s0; red[q][1][pl] = s1; red[q][2][pl] = s2; red[q][3][pl] = s3;
    __syncthreads();
    if (tid < 128) {
        int j = tid >> 5, pl2 = tid & 31;
        float r = 0.f;
        #pragma unroll
        for (int qq = 0; qq < 8; qq++) r += red[qq][j][pl2];
        g_t8[((size_t)n * 4 + j) * HW + blockIdx.x * 32 + pl2] = r;
    }
}

// ---------------------------------------------------------------------------
// gemm1: D rows = c' (A = t6 planes via cp.async), cols = m. K chunks of 32.
// grid (3, 32, 3) x 256, occ 2
// ---------------------------------------------------------------------------
__device__ __forceinline__ void g1_stageB(char* Bsp, const float* xb,
                                          const float* p2w, int m0, int p0, int tid) {
    int col4 = (tid & 7) * 4;
    int rbase = tid >> 3;
    #pragma unroll
    for (int pass = 0; pass < 4; pass++) {
        int mr = rbase + pass * 32;
        int m = m0 + mr, c = m / 3, k = m - 3 * c, sh = 2 * k - 2;
        float4 w4 = *reinterpret_cast<const float4*>(p2w + (size_t)m * HW + p0 + col4);
        int p = p0 + col4;
        int hh = p / 56 + sh;
        float v[4] = {0.f, 0.f, 0.f, 0.f};
        if (hh >= 0 && hh < 56) {
            float4 x4 = *reinterpret_cast<const float4*>(
                xb + (size_t)c * HW + p + sh * 56);
            v[0] = w4.x * x4.x; v[1] = w4.y * x4.y;
            v[2] = w4.z * x4.z; v[3] = w4.w * x4.w;
        }
        uint2 hi, lo; split4(v, hi, lo);
        char* bb = Bsp + mr * RS + col4 * 2;
        *(uint2*)(bb)      = hi;
        *(uint2*)(bb + 64) = lo;
    }
}

__global__ void __launch_bounds__(256, 2) gemm1_kernel(const float* __restrict__ x,
                                                       const float* __restrict__ p2w) {
    extern __shared__ char smem_raw[];
    char* smp = (char*)(((uintptr_t)smem_raw + 1023) & ~(uintptr_t)1023);

    const int tid = threadIdx.x, lane = tid & 31, wid = tid >> 5;
    const int wr = wid >> 1, wc = wid & 1;
    const int n = blockIdx.y, m0 = blockIdx.x * 128, s = blockIdx.z;

    const float* xb = x + (size_t)n * C * HW;
    const __nv_bfloat16* t6h = g_t6hi + (size_t)n * C * HW;
    const __nv_bfloat16* t6l = g_t6lo + (size_t)n * C * HW;

    float acc[2][8][4] = {};
    const int beg[4] = {0, 33, 66, 98};
    const int nch = beg[s + 1] - beg[s];
    const int pbase = beg[s] * 32;

    cpA(smp, t6h, t6l, HW, pbase, tid);
    CP_COMMIT();
    g1_stageB(smp + TILE_A, xb, p2w, m0, pbase, tid);
    CP_WAIT0();
    __syncthreads();

    for (int ch = 0; ch < nch; ch++) {
        char* cur = smp + (ch & 1) * STAGE1;
        bool more = ch + 1 < nch;
        char* nxt = smp + ((ch + 1) & 1) * STAGE1;
        int pn = pbase + (ch + 1) * 32;
        if (more) { cpA(nxt, t6h, t6l, HW, pn, tid); CP_COMMIT(); }
        mma_g1(smem_u32(cur), smem_u32(cur + TILE_A), wr, wc, lane, acc);
        if (more) g1_stageB(nxt + TILE_A, xb, p2w, m0, pn, tid);
        CP_WAIT0();
        __syncthreads();
    }

    const float SC = 9.1126371e-4f;   // 1/(sqrt(3136)*sqrt(384))
    float* ob = g_t7p + ((size_t)(s * NB + n)) * C * K3;
    #pragma unroll
    for (int mi = 0; mi < 2; mi++) {
        #pragma unroll
        for (int ni = 0; ni < 8; ni++) {
            int row = wr * 32 + mi * 16 + (lane >> 2);
            int col = m0 + wc * 64 + ni * 8 + (lane & 3) * 2;
            *(float2*)(ob + (size_t)row * K3 + col) =
                make_float2(acc[mi][ni][0] * SC, acc[mi][ni][1] * SC);
            *(float2*)(ob + (size_t)(row + 8) * K3 + col) =
                make_float2(acc[mi][ni][2] * SC, acc[mi][ni][3] * SC);
        }
    }
}

// ---------------------------------------------------------------------------
// t7sum: sum 3 partials, pack to hi/lo planes. grid 1536 x 256
// ---------------------------------------------------------------------------
__global__ void __launch_bounds__(256) t7sum_kernel() {
    size_t i = ((size_t)blockIdx.x * 256 + threadIdx.x) * 4;
    float4 v0 = *(const float4*)(g_t7p + i);
    float4 v1 = *(const float4*)(g_t7p + SPL + i);
    float4 v2 = *(const float4*)(g_t7p + 2 * SPL + i);
    float v[4] = {v0.x + v1.x + v2.x, v0.y + v1.y + v2.y,
                  v0.z + v1.z + v2.z, v0.w + v1.w + v2.w};
    uint2 hi, lo; split4(v, hi, lo);
    *(uint2*)(g_t7hi + i) = hi;
    *(uint2*)(g_t7lo + i) = lo;
}

// ---------------------------------------------------------------------------
// gemm2: persistent over 800 (n, p-tile) tiles, grid 592 x 256, occ 2.
// D rows = c (A = t7 planes via cp.async), cols = p (128-tile).
// B = unfold_w(x) staged transposed [m 32+32][p 128] with vectorized loads.
// ---------------------------------------------------------------------------
__device__ __forceinline__ void g2_stageB(char* Bsp, const float* xb,
                                          int p0, int m0c, int tid) {
    int mrow = tid & 31;
    int pq = tid >> 5;
    int m = m0c + mrow, cp = m / 3, k = m - 3 * cp, sh = 2 * k - 2;
    int pbase = p0 + pq * 16;
    const float* src = xb + (size_t)cp * HW + pbase + sh;

    float v[16];
    #pragma unroll
    for (int j = 0; j < 8; j++) {
        int p = pbase + 2 * j;
        int wcol = p % 56;
        int ww = wcol + sh;
        bool ok = (p < HW) && (ww >= 0) && (ww < 56);
        float2 f = ok ? *(const float2*)(src + 2 * j) : make_float2(0.f, 0.f);
        v[2 * j] = f.x; v[2 * j + 1] = f.y;
    }
    uint2 hi[4], lo[4];
    #pragma unroll
    for (int q = 0; q < 4; q++) split4(v + 4 * q, hi[q], lo[q]);
    char* bh = Bsp + mrow * RSB + pq * 32;
    char* bl = Bsp + (32 + mrow) * RSB + pq * 32;
    *(uint4*)(bh)      = make_uint4(hi[0].x, hi[0].y, hi[1].x, hi[1].y);
    *(uint4*)(bh + 16) = make_uint4(hi[2].x, hi[2].y, hi[3].x, hi[3].y);
    *(uint4*)(bl)      = make_uint4(lo[0].x, lo[0].y, lo[1].x, lo[1].y);
    *(uint4*)(bl + 16) = make_uint4(lo[2].x, lo[2].y, lo[3].x, lo[3].y);
}

__global__ void __launch_bounds__(256, 2) gemm2_kernel(const float* __restrict__ x,
                                                       float* __restrict__ out) {
    extern __shared__ char smem_raw[];
    char* smp = (char*)(((uintptr_t)smem_raw + 1023) & ~(uintptr_t)1023);

    const int tid = threadIdx.x, lane = tid & 31, wid = tid >> 5;
    const int wr = wid >> 1, wc = wid & 1;
    const int NCH = 12;

    for (int tile = blockIdx.x; tile < G2_TILES; tile += G2_GRID) {
        const int n = tile / 25;
        const int p0 = (tile - n * 25) * 128;

        const float* xb = x + (size_t)n * C * HW;
        const __nv_bfloat16* t7h = g_t7hi + (size_t)n * C * K3;
        const __nv_bfloat16* t7l = g_t7lo + (size_t)n * C * K3;

        float acc[2][8][4] = {};

        cpA(smp, t7h, t7l, K3, 0, tid);
        CP_COMMIT();
        g2_stageB(smp + TILE_A, xb, p0, 0, tid);
        CP_WAIT0();
        __syncthreads();

        for (int ch = 0; ch < NCH; ch++) {
            char* cur = smp + (ch & 1) * STAGE2;
            bool more = ch + 1 < NCH;
            char* nxt = smp + ((ch + 1) & 1) * STAGE2;
            int mn = (ch + 1) * 32;
            if (more) { cpA(nxt, t7h, t7l, K3, mn, tid); CP_COMMIT(); }
            mma_g2(smem_u32(cur), smem_u32(cur + TILE_A), wr, wc, lane, acc);
            if (more) g2_stageB(nxt + TILE_A, xb, p0, mn, tid);
            CP_WAIT0();
            __syncthreads();
        }

        // epilogue: out = acc + x * t8[c%4]
        const float* t8b = g_t8 + (size_t)n * 4 * HW;
        float* outb = out + (size_t)n * C * HW;
        #pragma unroll
        for (int mi = 0; mi < 2; mi++) {
            #pragma unroll
            for (int ni = 0; ni < 8; ni++) {
                int c = wr * 32 + mi * 16 + (lane >> 2);
                int p = p0 + wc * 64 + ni * 8 + (lane & 3) * 2;
                if (p < HW) {
                    #pragma unroll
                    for (int h = 0; h < 2; h++) {
                        int cc = c + h * 8;
                        float2 xv  = *(const float2*)(xb  + (size_t)cc * HW + p);
                        float2 t8v = *(const float2*)(t8b + (size_t)(cc & 3) * HW + p);
                        float2 o = make_float2(acc[mi][ni][2 * h]     + xv.x * t8v.x,
                                               acc[mi][ni][2 * h + 1] + xv.y * t8v.y);
                        *(float2*)(outb + (size_t)cc * HW + p) = o;
                    }
                }
            }
        }
        __syncthreads();   // smem safe before next tile's prologue
    }
}

// ---------------------------------------------------------------------------
extern "C" void kernel_launch(void* const* d_in, const int* in_sizes, int n_in,
                              void* d_out, int out_size) {
    const float* x      = (const float*)d_in[0];
    const float* p2w    = (const float*)d_in[1];
    const float* p5w    = (const float*)d_in[2];
    const float* conv_w = (const float*)d_in[3];
    float* out = (float*)d_out;

    cudaFuncSetAttribute(gemm1_kernel, cudaFuncAttributeMaxDynamicSharedMemorySize, SMEM1);
    cudaFuncSetAttribute(gemm2_kernel, cudaFuncAttributeMaxDynamicSharedMemorySize, SMEM2);

    prep_kernel<<<dim3(98, NB), 256>>>(x, p5w, conv_w);
    gemm1_kernel<<<dim3(3, NB, NSPLIT), 256, SMEM1>>>(x, p2w);
    t7sum_kernel<<<1536, 256>>>();
    gemm2_kernel<<<G2_GRID, 256, SMEM2>>>(x, out);
}